// round 14
// baseline (speedup 1.0000x reference)
#include <cuda_runtime.h>
#include <cuda_bf16.h>
#include <math.h>
#include <stdint.h>

// ---------------- problem constants ----------------
#define BB 8
#define NN 5000
#define EE 80000
#define IND 30
#define HH 4
#define DD 64
#define HD 256
#define OUTD 3
#define TSTEPS 5
#define EPSBN 1e-5f
#define MROWS (BB*NN)   // 40000

// GEMM tiling (R10-proven): CTA 128x128, 512 threads, warp 32x32
#define TM 128
#define TN 128
#define KC 64
#define ASTR 72
#define BSTR 264
#define NPART 32
#define FC_ROWS 32

#define B_BYTES (128 * BSTR * 2)
#define A_BYTES (128 * ASTR * 2)
#define GSM_BYTES (2 * B_BYTES + 4 * A_BYTES)   // 208896

// ---------------- device scratch ----------------
__device__ float g_x[MROWS * IND];
__device__ float g_h[MROWS * HD];
__device__ float g_hout[MROWS * HD];
__device__ float g_el[MROWS * HH];
__device__ float g_er[MROWS * HH];
__device__ int   g_rowstart[NN + 1];
__device__ int   g_csr_src[EE];
__device__ float g_part[NPART * HD];
__device__ float g_partsq[NPART * HD];
__device__ float g_scale[HD];
__device__ float g_shift[HD];
__device__ unsigned g_ctr;
__device__ __nv_bfloat16 g_wthi[3 * HD * HD];
__device__ __nv_bfloat16 g_wtlo[3 * HD * HD];

__device__ __forceinline__ uint32_t s2u(const void* p) {
    uint32_t a;
    asm("{ .reg .u64 t; cvta.to.shared.u64 t, %1; cvt.u32.u64 %0, t; }" : "=r"(a) : "l"(p));
    return a;
}
__device__ __forceinline__ void ldsm4(uint32_t* r, uint32_t a) {
    asm volatile("ldmatrix.sync.aligned.m8n8.x4.shared.b16 {%0,%1,%2,%3}, [%4];"
                 : "=r"(r[0]), "=r"(r[1]), "=r"(r[2]), "=r"(r[3]) : "r"(a));
}
__device__ __forceinline__ void mma16816(float* c, const uint32_t* a, const uint32_t* b) {
    asm volatile(
        "mma.sync.aligned.m16n8k16.row.col.f32.bf16.bf16.f32 "
        "{%0,%1,%2,%3}, {%4,%5,%6,%7}, {%8,%9}, {%0,%1,%2,%3};"
        : "+f"(c[0]), "+f"(c[1]), "+f"(c[2]), "+f"(c[3])
        : "r"(a[0]), "r"(a[1]), "r"(a[2]), "r"(a[3]), "r"(b[0]), "r"(b[1]));
}
__device__ __forceinline__ float4 lrelu4(float4 a, float s) {
    a.x = a.x > 0.f ? a.x : s * a.x;
    a.y = a.y > 0.f ? a.y : s * a.y;
    a.z = a.z > 0.f ? a.z : s * a.z;
    a.w = a.w > 0.f ? a.w : s * a.w;
    return a;
}

// ---------------- CSR build (single block) ----------------
__global__ __launch_bounds__(1024) void k_csr(const int* __restrict__ src,
                                              const int* __restrict__ dst) {
    __shared__ int s_start[NN];
    __shared__ int s_tmp[1024];
    const int t = threadIdx.x;

    for (int i = t; i < NN; i += 1024) s_start[i] = 0;
    __syncthreads();
    for (int e = t; e < EE; e += 1024) atomicAdd(&s_start[dst[e]], 1);
    __syncthreads();

    int carry = 0;
    for (int base = 0; base < NN; base += 1024) {
        int v = (base + t < NN) ? s_start[base + t] : 0;
        s_tmp[t] = v;
        __syncthreads();
        for (int off = 1; off < 1024; off <<= 1) {
            int x = (t >= off) ? s_tmp[t - off] : 0;
            __syncthreads();
            s_tmp[t] += x;
            __syncthreads();
        }
        int incl = s_tmp[t];
        int tot = s_tmp[1023];
        __syncthreads();
        if (base + t < NN) {
            int ex = carry + incl - v;
            s_start[base + t] = ex;
            g_rowstart[base + t] = ex;
        }
        carry += tot;
    }
    if (t == 0) { g_rowstart[NN] = carry; g_ctr = 0; }
    __syncthreads();

    for (int e = t; e < EE; e += 1024) {
        int v = dst[e];
        int p = atomicAdd(&s_start[v], 1);
        g_csr_src[p] = src[e];
    }
}

__global__ void k_copyx(const float* __restrict__ xx) {
    int i = blockIdx.x * blockDim.x + threadIdx.x;
    if (i < MROWS * IND) g_x[i] = xx[i];
}

// ---------------- W transpose + bf16 split ----------------
__global__ void k_wprep(const float* __restrict__ W1, const float* __restrict__ W2,
                        const float* __restrict__ W3) {
    int k = blockIdx.x;
    int l = blockIdx.y;
    int n = threadIdx.x;
    const float* W = (l == 0) ? W1 : (l == 1) ? W2 : W3;
    float v = W[k * HD + n];
    __nv_bfloat16 h = __float2bfloat16(v);
    float lo = v - __bfloat162float(h);
    int o = l * HD * HD + n * HD + k;
    g_wthi[o] = h;
    g_wtlo[o] = __float2bfloat16(lo);
}

// ---------------- layer-0 FC (32 rows/block) ----------------
__global__ __launch_bounds__(256) void k_fc0(const float* __restrict__ W,
                                             const float* __restrict__ al,
                                             const float* __restrict__ ar) {
    __shared__ float sW[IND * HD];
    __shared__ float sx[FC_ROWS * IND];
    __shared__ float pel[FC_ROWS][8], per_[FC_ROWS][8];
    const int t = threadIdx.x;
    const int m0 = blockIdx.x * FC_ROWS;
    const int w = t >> 5, lane = t & 31;

    for (int i = t; i < IND * HD; i += 256) sW[i] = W[i];
    for (int i = t; i < FC_ROWS * IND; i += 256) sx[i] = g_x[m0 * IND + i];
    __syncthreads();

    const float alv = __ldg(&al[t]);
    const float arv = __ldg(&ar[t]);

#pragma unroll
    for (int r = 0; r < FC_ROWS; r++) {
        float acc = 0.f;
#pragma unroll
        for (int k = 0; k < IND; k++) acc = fmaf(sx[r * IND + k], sW[k * HD + t], acc);
        g_h[(size_t)(m0 + r) * HD + t] = acc;
        float ve = acc * alv, vr = acc * arv;
#pragma unroll
        for (int off = 16; off; off >>= 1) {
            ve += __shfl_xor_sync(0xffffffffu, ve, off);
            vr += __shfl_xor_sync(0xffffffffu, vr, off);
        }
        if (lane == 0) { pel[r][w] = ve; per_[r][w] = vr; }
    }
    __syncthreads();
    if (t < FC_ROWS * HH) {
        int r = t >> 2, h = t & 3;
        g_el[(m0 + r) * HH + h] = pel[r][2 * h] + pel[r][2 * h + 1];
        g_er[(m0 + r) * HH + h] = per_[r][2 * h] + per_[r][2 * h + 1];
    }
}

// ---------------- HMMA GEMM (R10 exact): 512 threads, warp 32x32 ----------------
__global__ __launch_bounds__(512) void k_gemm(int wsel, const float* __restrict__ al,
                                              const float* __restrict__ ar) {
    extern __shared__ char sm[];
    __shared__ float s_sc[HD], s_sh[HD];
    __shared__ float sh_e[2][128][2][2];
    __nv_bfloat16* Bhi = (__nv_bfloat16*)sm;
    __nv_bfloat16* Blo = Bhi + 128 * BSTR;
    __nv_bfloat16* Abase = Blo + 128 * BSTR;
    const uint32_t uBhi = s2u(Bhi), uBlo = s2u(Blo);
    const uint32_t uA = s2u(Abase);

    const int t = threadIdx.x;
    const int lane = t & 31, warp = t >> 5;
    const int bx = blockIdx.x, by = blockIdx.y;
    const int row0 = by * TM, col0 = bx * TN;
    const int warp_m = (warp >> 2) * 32;
    const int warp_n = (warp & 3) * 32;
    const int head2 = (warp & 3) >> 1;
    const int halfid = warp & 1;
    const int head = bx * 2 + head2;

    if (t < HD) { s_sc[t] = g_scale[t]; s_sh[t] = g_shift[t]; }
    __syncthreads();

    const __nv_bfloat16* wh = g_wthi + wsel * HD * HD;
    const __nv_bfloat16* wl = g_wtlo + wsel * HD * HD;

    {
        int n = t >> 2, kq = (t & 3) * 64;
        int gn = col0 + n;
        const uint4* ph = (const uint4*)&wh[gn * HD + kq];
        const uint4* pl = (const uint4*)&wl[gn * HD + kq];
#pragma unroll
        for (int q = 0; q < 8; q++) {
            *(uint4*)&Bhi[n * BSTR + kq + 8 * q] = __ldg(&ph[q]);
            *(uint4*)&Blo[n * BSTR + kq + 8 * q] = __ldg(&pl[q]);
        }
    }

    float c[2][4][4];
#pragma unroll
    for (int i = 0; i < 2; i++)
#pragma unroll
        for (int j = 0; j < 4; j++)
#pragma unroll
            for (int q = 0; q < 4; q++) c[i][j][q] = 0.f;

    const int a_row = ((lane >> 3) & 1) * 8 + (lane & 7);
    const int a_kof = (lane >> 4) * 8;
    const int b_nsel = (lane >> 4) & 1;
    const int b_ksel = (lane >> 3) & 1;
    const int b_row = (lane & 7);

    auto convA = [&](int ch, int bf) {
        __nv_bfloat16* Ahi = Abase + bf * 2 * 128 * ASTR;
        __nv_bfloat16* Alo = Ahi + 128 * ASTR;
        const int k0 = ch * KC;
        int r = t >> 2, c0i = (t & 3) * 16;
        int grow = row0 + r;
        float x[16];
        if (grow < MROWS) {
            const float4* p = (const float4*)&g_hout[(size_t)grow * HD + k0 + c0i];
#pragma unroll
            for (int q = 0; q < 4; q++) {
                float4 v = p[q];
                x[4 * q + 0] = v.x; x[4 * q + 1] = v.y; x[4 * q + 2] = v.z; x[4 * q + 3] = v.w;
            }
        } else {
#pragma unroll
            for (int j = 0; j < 16; j++) x[j] = 0.f;
        }
#pragma unroll
        for (int j = 0; j < 16; j++) {
            float v = fmaf(x[j], s_sc[k0 + c0i + j], s_sh[k0 + c0i + j]);
            x[j] = v > 0.f ? v : 0.01f * v;
        }
#pragma unroll
        for (int q = 0; q < 2; q++) {
            union { __nv_bfloat16 b[8]; uint4 u; } uh, ul;
#pragma unroll
            for (int j = 0; j < 8; j++) {
                float xv = x[8 * q + j];
                __nv_bfloat16 h = __float2bfloat16(xv);
                uh.b[j] = h;
                ul.b[j] = __float2bfloat16(xv - __bfloat162float(h));
            }
            *(uint4*)&Ahi[r * ASTR + c0i + 8 * q] = uh.u;
            *(uint4*)&Alo[r * ASTR + c0i + 8 * q] = ul.u;
        }
    };

    convA(0, 0);
    __syncthreads();

    for (int ch = 0; ch < 4; ch++) {
        const int bf = ch & 1;
        const uint32_t uAhi = uA + (uint32_t)(bf * 2 * 128 * ASTR * 2);
        const uint32_t uAlo = uAhi + 128 * ASTR * 2;
#pragma unroll
        for (int ks = 0; ks < 4; ks++) {
            const int kg = ch * 4 + ks;
            uint32_t afh[2][4], afl[2][4];
            uint32_t bfh[4][2], bfl[4][2];
#pragma unroll
            for (int mt = 0; mt < 2; mt++) {
                uint32_t off = (uint32_t)(((warp_m + mt * 16 + a_row) * ASTR + 16 * ks + a_kof) * 2);
                ldsm4(afh[mt], uAhi + off);
                ldsm4(afl[mt], uAlo + off);
            }
#pragma unroll
            for (int p = 0; p < 2; p++) {
                uint32_t off = (uint32_t)(((warp_n + (2 * p + b_nsel) * 8 + b_row) * BSTR + 16 * kg + 8 * b_ksel) * 2);
                uint32_t r4[4];
                ldsm4(r4, uBhi + off);
                bfh[2 * p][0] = r4[0]; bfh[2 * p][1] = r4[1];
                bfh[2 * p + 1][0] = r4[2]; bfh[2 * p + 1][1] = r4[3];
                ldsm4(r4, uBlo + off);
                bfl[2 * p][0] = r4[0]; bfl[2 * p][1] = r4[1];
                bfl[2 * p + 1][0] = r4[2]; bfl[2 * p + 1][1] = r4[3];
            }
#pragma unroll
            for (int mt = 0; mt < 2; mt++)
#pragma unroll
                for (int nt = 0; nt < 4; nt++) {
                    mma16816(c[mt][nt], afh[mt], bfh[nt]);
                    mma16816(c[mt][nt], afh[mt], bfl[nt]);
                    mma16816(c[mt][nt], afl[mt], bfh[nt]);
                }
        }
        if (ch < 3) {
            convA(ch + 1, (ch + 1) & 1);
            __syncthreads();
        }
    }

    float elacc[2][2] = {{0.f, 0.f}, {0.f, 0.f}};
    float eracc[2][2] = {{0.f, 0.f}, {0.f, 0.f}};
    const int qn = 2 * (lane & 3);
    const int g = lane >> 2;
#pragma unroll
    for (int mt = 0; mt < 2; mt++) {
#pragma unroll
        for (int nt = 0; nt < 4; nt++) {
            float v0 = c[mt][nt][0], v1 = c[mt][nt][1];
            float v2 = c[mt][nt][2], v3 = c[mt][nt][3];
            int cih = nt * 8 + qn;
            int hcol = halfid * 32 + cih;
            float a0 = __ldg(&al[head * DD + hcol]), a1 = __ldg(&al[head * DD + hcol + 1]);
            float r0 = __ldg(&ar[head * DD + hcol]), r1 = __ldg(&ar[head * DD + hcol + 1]);
            elacc[mt][0] = fmaf(v0, a0, fmaf(v1, a1, elacc[mt][0]));
            elacc[mt][1] = fmaf(v2, a0, fmaf(v3, a1, elacc[mt][1]));
            eracc[mt][0] = fmaf(v0, r0, fmaf(v1, r1, eracc[mt][0]));
            eracc[mt][1] = fmaf(v2, r0, fmaf(v3, r1, eracc[mt][1]));
            int gcol = col0 + warp_n + cih;
            int grow0 = row0 + warp_m + mt * 16 + g;
            int grow1 = grow0 + 8;
            if (grow0 < MROWS) *(float2*)&g_h[(size_t)grow0 * HD + gcol] = make_float2(v0, v1);
            if (grow1 < MROWS) *(float2*)&g_h[(size_t)grow1 * HD + gcol] = make_float2(v2, v3);
        }
    }
#pragma unroll
    for (int mt = 0; mt < 2; mt++)
#pragma unroll
        for (int half = 0; half < 2; half++) {
            float e = elacc[mt][half], r = eracc[mt][half];
            e += __shfl_xor_sync(0xffffffffu, e, 1);
            e += __shfl_xor_sync(0xffffffffu, e, 2);
            r += __shfl_xor_sync(0xffffffffu, r, 1);
            r += __shfl_xor_sync(0xffffffffu, r, 2);
            if ((lane & 3) == 0) {
                int rr = warp_m + mt * 16 + half * 8 + g;
                sh_e[0][rr][head2][halfid] = e;
                sh_e[1][rr][head2][halfid] = r;
            }
        }
    __syncthreads();
    if (t < 256) {
        int rr = t & 127, h2 = t >> 7;
        int row = row0 + rr;
        if (row < MROWS) {
            g_el[row * HH + bx * 2 + h2] = sh_e[0][rr][h2][0] + sh_e[0][rr][h2][1];
            g_er[row * HH + bx * 2 + h2] = sh_e[1][rr][h2][0] + sh_e[1][rr][h2][1];
        }
    }
}

// ---------------- agg + fused BN finalize (last-CTA pattern) ----------------
__global__ __launch_bounds__(256) void k_agg(const float* __restrict__ gamma,
                                             const float* __restrict__ beta) {
    __shared__ float sh_a[8][32][4];
    __shared__ int   sh_src[8][32];
    __shared__ float sh_ws[8][HD];
    __shared__ float sh_wq[8][HD];
    __shared__ bool  s_last;

    const int t = threadIdx.x;
    const int w = t >> 5, lane = t & 31;
    const int bn = blockIdx.x * 8 + w;
    const int b = bn / NN, v = bn - b * NN;
    const int rowbase = b * NN;
    const int e0 = g_rowstart[v];
    const int deg = g_rowstart[v + 1] - e0;
    const int hc = lane >> 3;
    const int c0 = lane * 8;

    float4 accA = make_float4(0.f, 0.f, 0.f, 0.f);
    float4 accB = make_float4(0.f, 0.f, 0.f, 0.f);

    if (deg > 0) {
        const float4 erv = *(const float4*)&g_er[bn * HH];

        const bool has0 = lane < deg;
        int s0c = 0;
        float4 e0c = make_float4(-INFINITY, -INFINITY, -INFINITY, -INFINITY);
        if (has0) {
            s0c = g_csr_src[e0 + lane];
            float4 el = *(const float4*)&g_el[(rowbase + s0c) * HH];
            e0c = lrelu4(make_float4(el.x + erv.x, el.y + erv.y, el.z + erv.z, el.w + erv.w), 0.2f);
        }
        float4 m4 = e0c;
        for (int i = lane + 32; i < deg; i += 32) {
            int s = g_csr_src[e0 + i];
            float4 el = *(const float4*)&g_el[(rowbase + s) * HH];
            float4 e = lrelu4(make_float4(el.x + erv.x, el.y + erv.y, el.z + erv.z, el.w + erv.w), 0.2f);
            m4.x = fmaxf(m4.x, e.x); m4.y = fmaxf(m4.y, e.y);
            m4.z = fmaxf(m4.z, e.z); m4.w = fmaxf(m4.w, e.w);
        }
#pragma unroll
        for (int off = 16; off; off >>= 1) {
            m4.x = fmaxf(m4.x, __shfl_xor_sync(0xffffffffu, m4.x, off));
            m4.y = fmaxf(m4.y, __shfl_xor_sync(0xffffffffu, m4.y, off));
            m4.z = fmaxf(m4.z, __shfl_xor_sync(0xffffffffu, m4.z, off));
            m4.w = fmaxf(m4.w, __shfl_xor_sync(0xffffffffu, m4.w, off));
        }
        float4 s4 = make_float4(0.f, 0.f, 0.f, 0.f);
        if (has0) {
            float4 p = make_float4(__expf(e0c.x - m4.x), __expf(e0c.y - m4.y),
                                   __expf(e0c.z - m4.z), __expf(e0c.w - m4.w));
            s4 = p;
            sh_src[w][lane] = s0c;
            *(float4*)&sh_a[w][lane][0] = p;
        }
        for (int i = lane + 32; i < deg; i += 32) {
            int s = g_csr_src[e0 + i];
            float4 el = *(const float4*)&g_el[(rowbase + s) * HH];
            float4 e = lrelu4(make_float4(el.x + erv.x, el.y + erv.y, el.z + erv.z, el.w + erv.w), 0.2f);
            s4.x += __expf(e.x - m4.x); s4.y += __expf(e.y - m4.y);
            s4.z += __expf(e.z - m4.z); s4.w += __expf(e.w - m4.w);
        }
#pragma unroll
        for (int off = 16; off; off >>= 1) {
            s4.x += __shfl_xor_sync(0xffffffffu, s4.x, off);
            s4.y += __shfl_xor_sync(0xffffffffu, s4.y, off);
            s4.z += __shfl_xor_sync(0xffffffffu, s4.z, off);
            s4.w += __shfl_xor_sync(0xffffffffu, s4.w, off);
        }
        const float inv = 1.f / (hc == 0 ? s4.x : hc == 1 ? s4.y : hc == 2 ? s4.z : s4.w);
        const float mh  = (hc == 0 ? m4.x : hc == 1 ? m4.y : hc == 2 ? m4.z : m4.w);
        const float erh = (hc == 0 ? erv.x : hc == 1 ? erv.y : hc == 2 ? erv.z : erv.w);
        __syncwarp();

        const float* hb = g_h + (((size_t)rowbase) << 8) + c0;
        float4 acc2 = make_float4(0.f, 0.f, 0.f, 0.f);
        float4 acc3 = make_float4(0.f, 0.f, 0.f, 0.f);
        const int lim = min(deg, 32);
        int i = 0;
        for (; i + 4 <= lim; i += 4) {
            int sa = sh_src[w][i],     sb = sh_src[w][i + 1];
            int sc = sh_src[w][i + 2], sd = sh_src[w][i + 3];
            float wa = sh_a[w][i][hc] * inv,     wb = sh_a[w][i + 1][hc] * inv;
            float wc = sh_a[w][i + 2][hc] * inv, wd = sh_a[w][i + 3][hc] * inv;
            const float4* pa = (const float4*)(hb + ((size_t)sa << 8));
            const float4* pb = (const float4*)(hb + ((size_t)sb << 8));
            const float4* pc = (const float4*)(hb + ((size_t)sc << 8));
            const float4* pd = (const float4*)(hb + ((size_t)sd << 8));
            float4 a0 = pa[0], a1 = pa[1], b0 = pb[0], b1 = pb[1];
            float4 c0v = pc[0], c1 = pc[1], d0 = pd[0], d1 = pd[1];
            accA.x = fmaf(wa, a0.x, accA.x); accA.y = fmaf(wa, a0.y, accA.y);
            accA.z = fmaf(wa, a0.z, accA.z); accA.w = fmaf(wa, a0.w, accA.w);
            accB.x = fmaf(wa, a1.x, accB.x); accB.y = fmaf(wa, a1.y, accB.y);
            accB.z = fmaf(wa, a1.z, accB.z); accB.w = fmaf(wa, a1.w, accB.w);
            acc2.x = fmaf(wb, b0.x, acc2.x); acc2.y = fmaf(wb, b0.y, acc2.y);
            acc2.z = fmaf(wb, b0.z, acc2.z); acc2.w = fmaf(wb, b0.w, acc2.w);
            acc3.x = fmaf(wb, b1.x, acc3.x); acc3.y = fmaf(wb, b1.y, acc3.y);
            acc3.z = fmaf(wb, b1.z, acc3.z); acc3.w = fmaf(wb, b1.w, acc3.w);
            accA.x = fmaf(wc, c0v.x, accA.x); accA.y = fmaf(wc, c0v.y, accA.y);
            accA.z = fmaf(wc, c0v.z, accA.z); accA.w = fmaf(wc, c0v.w, accA.w);
            accB.x = fmaf(wc, c1.x, accB.x); accB.y = fmaf(wc, c1.y, accB.y);
            accB.z = fmaf(wc, c1.z, accB.z); accB.w = fmaf(wc, c1.w, accB.w);
            acc2.x = fmaf(wd, d0.x, acc2.x); acc2.y = fmaf(wd, d0.y, acc2.y);
            acc2.z = fmaf(wd, d0.z, acc2.z); acc2.w = fmaf(wd, d0.w, acc2.w);
            acc3.x = fmaf(wd, d1.x, acc3.x); acc3.y = fmaf(wd, d1.y, acc3.y);
            acc3.w = fmaf(wd, d1.w, acc3.w); acc3.z = fmaf(wd, d1.z, acc3.z);
        }
        for (; i < lim; i++) {
            int s = sh_src[w][i];
            float wv = sh_a[w][i][hc] * inv;
            const float4* p = (const float4*)(hb + ((size_t)s << 8));
            float4 h0 = p[0], h1 = p[1];
            accA.x = fmaf(wv, h0.x, accA.x); accA.y = fmaf(wv, h0.y, accA.y);
            accA.z = fmaf(wv, h0.z, accA.z); accA.w = fmaf(wv, h0.w, accA.w);
            accB.x = fmaf(wv, h1.x, accB.x); accB.y = fmaf(wv, h1.y, accB.y);
            accB.z = fmaf(wv, h1.z, accB.z); accB.w = fmaf(wv, h1.w, accB.w);
        }
        for (i = 32; i < deg; i++) {
            int s = g_csr_src[e0 + i];
            float4 el = *(const float4*)&g_el[(rowbase + s) * HH];
            float e = (hc == 0 ? el.x : hc == 1 ? el.y : hc == 2 ? el.z : el.w) + erh;
            e = e > 0.f ? e : 0.2f * e;
            float wv = __expf(e - mh) * inv;
            const float4* p = (const float4*)(hb + ((size_t)s << 8));
            float4 h0 = p[0], h1 = p[1];
            accA.x = fmaf(wv, h0.x, accA.x); accA.y = fmaf(wv, h0.y, accA.y);
            accA.z = fmaf(wv, h0.z, accA.z); accA.w = fmaf(wv, h0.w, accA.w);
            accB.x = fmaf(wv, h1.x, accB.x); accB.y = fmaf(wv, h1.y, accB.y);
            accB.z = fmaf(wv, h1.z, accB.z); accB.w = fmaf(wv, h1.w, accB.w);
        }
        accA.x += acc2.x; accA.y += acc2.y; accA.z += acc2.z; accA.w += acc2.w;
        accB.x += acc3.x; accB.y += acc3.y; accB.z += acc3.z; accB.w += acc3.w;
    }

    float* outp = g_hout + (size_t)bn * HD + c0;
    *(float4*)outp = accA;
    *(float4*)(outp + 4) = accB;

    *(float4*)&sh_ws[w][c0]     = accA;
    *(float4*)&sh_ws[w][c0 + 4] = accB;
    *(float4*)&sh_wq[w][c0]     = make_float4(accA.x * accA.x, accA.y * accA.y,
                                              accA.z * accA.z, accA.w * accA.w);
    *(float4*)&sh_wq[w][c0 + 4] = make_float4(accB.x * accB.x, accB.y * accB.y,
                                              accB.z * accB.z, accB.w * accB.w);
    __syncthreads();
    if (t < HD) {
        float s = 0.f, sq = 0.f;
#pragma unroll
        for (int wi = 0; wi < 8; wi++) { s += sh_ws[wi][t]; sq += sh_wq[wi][t]; }
        int slot = (blockIdx.x & (NPART - 1)) * HD + t;
        atomicAdd(&g_part[slot], s);
        atomicAdd(&g_partsq[slot], sq);
    }

    // ---- last CTA finalizes BN scale/shift ----
    __threadfence();
    __syncthreads();
    if (t == 0) {
        unsigned old = atomicAdd(&g_ctr, 1u);
        s_last = (old == gridDim.x - 1);
    }
    __syncthreads();
    if (s_last) {
        if (t == 0) g_ctr = 0;
        if (t < HD) {
            float s = 0.f, sq = 0.f;
#pragma unroll
            for (int i = 0; i < NPART; i++) {
                s  += g_part[i * HD + t];
                sq += g_partsq[i * HD + t];
                g_part[i * HD + t] = 0.f;
                g_partsq[i * HD + t] = 0.f;
            }
            float inv = 1.f / (float)MROWS;
            float mu = s * inv;
            float var = sq * inv - mu * mu;
            float sc = __ldg(&gamma[t]) * rsqrtf(var + EPSBN);
            g_scale[t] = sc;
            g_shift[t] = __ldg(&beta[t]) - mu * sc;
        }
    }
}

// ---------------- output projection: warp per node, 8 nodes/CTA ----------------
__global__ __launch_bounds__(256) void k_proj(const float* __restrict__ Wo,
                                              const float* __restrict__ bo,
                                              float* __restrict__ out, int step) {
    __shared__ float sWo[HD * OUTD];
    const int t = threadIdx.x;
    const int lane = t & 31;
    const int bn = blockIdx.x * 8 + (t >> 5);

    for (int i = t; i < HD * OUTD; i += 256) sWo[i] = Wo[i];
    __syncthreads();

    const float* hp = g_hout + (size_t)bn * HD;
    float s0 = 0.f, s1 = 0.f, s2 = 0.f;
#pragma unroll
    for (int q = 0; q < 8; q++) {
        int k = lane * 8 + q;
        float xv = fmaf(hp[k], g_scale[k], g_shift[k]);
        xv = xv > 0.f ? xv : 0.01f * xv;
        s0 = fmaf(xv, sWo[k * OUTD + 0], s0);
        s1 = fmaf(xv, sWo[k * OUTD + 1], s1);
        s2 = fmaf(xv, sWo[k * OUTD + 2], s2);
    }
#pragma unroll
    for (int off = 16; off; off >>= 1) {
        s0 += __shfl_xor_sync(0xffffffffu, s0, off);
        s1 += __shfl_xor_sync(0xffffffffu, s1, off);
        s2 += __shfl_xor_sync(0xffffffffu, s2, off);
    }
    s0 += __ldg(&bo[0]); s1 += __ldg(&bo[1]); s2 += __ldg(&bo[2]);

    float keep = 0.f;
    if (lane < IND - OUTD) keep = g_x[bn * IND + lane + OUTD];
    __syncwarp();
    if (lane < IND - OUTD) g_x[bn * IND + lane] = keep;
    else if (lane < IND) g_x[bn * IND + lane] = (lane == 27 ? s0 : lane == 28 ? s1 : s2);
    if (lane < OUTD) out[(bn * TSTEPS + step) * OUTD + lane] = (lane == 0 ? s0 : lane == 1 ? s1 : s2);
}

// ---------------- launcher ----------------
extern "C" void kernel_launch(void* const* d_in, const int* in_sizes, int n_in,
                              void* d_out, int out_size) {
    const float* xx  = (const float*)d_in[0];
    const int*   src = (const int*)d_in[1];
    const int*   dst = (const int*)d_in[2];
    const float *W[4], *al[4], *ar[4], *gamma[4], *beta[4];
    for (int l = 0; l < 4; l++) {
        W[l]     = (const float*)d_in[3 + 5 * l];
        al[l]    = (const float*)d_in[4 + 5 * l];
        ar[l]    = (const float*)d_in[5 + 5 * l];
        gamma[l] = (const float*)d_in[6 + 5 * l];
        beta[l]  = (const float*)d_in[7 + 5 * l];
    }
    const float* W_out = (const float*)d_in[23];
    const float* b_out = (const float*)d_in[24];
    float* out = (float*)d_out;

    cudaFuncSetAttribute(k_gemm, cudaFuncAttributeMaxDynamicSharedMemorySize, GSM_BYTES);

    dim3 ggrid(HD / TN, (MROWS + TM - 1) / TM);   // (2, 313)

    k_csr<<<1, 1024>>>(src, dst);                                // 1
    k_copyx<<<(MROWS * IND + 255) / 256, 256>>>(xx);             // 2
    k_fc0<<<MROWS / FC_ROWS, 256>>>(W[0], al[0], ar[0]);         // 3
    k_agg<<<MROWS / 8, 256>>>(gamma[0], beta[0]);                // 4  <-- profiled
    k_wprep<<<dim3(HD, 3), HD>>>(W[1], W[2], W[3]);              // 5
    for (int l = 1; l < 4; l++) {
        k_gemm<<<ggrid, 512, GSM_BYTES>>>(l - 1, al[l], ar[l]);
        k_agg<<<MROWS / 8, 256>>>(gamma[l], beta[l]);
    }
    k_proj<<<MROWS / 8, 256>>>(W_out, b_out, out, 0);

    for (int step = 1; step < TSTEPS; step++) {
        for (int l = 0; l < 4; l++) {
            if (l == 0)
                k_fc0<<<MROWS / FC_ROWS, 256>>>(W[0], al[0], ar[0]);
            else
                k_gemm<<<ggrid, 512, GSM_BYTES>>>(l - 1, al[l], ar[l]);
            k_agg<<<MROWS / 8, 256>>>(gamma[l], beta[l]);
        }
        k_proj<<<MROWS / 8, 256>>>(W_out, b_out, out, step);
    }
}

// round 15
// speedup vs baseline: 1.0382x; 1.0382x over previous
#include <cuda_runtime.h>
#include <cuda_bf16.h>
#include <math.h>
#include <stdint.h>

// ---------------- problem constants ----------------
#define BB 8
#define NN 5000
#define EE 80000
#define IND 30
#define HH 4
#define DD 64
#define HD 256
#define OUTD 3
#define TSTEPS 5
#define EPSBN 1e-5f
#define MROWS (BB*NN)   // 40000

// GEMM tiling (R10-proven): CTA 128x128, 512 threads, warp 32x32
#define TM 128
#define TN 128
#define KC 64
#define ASTR 72
#define BSTR 264
#define NPART 32
#define FC_ROWS 32

#define B_BYTES (128 * BSTR * 2)
#define A_BYTES (128 * ASTR * 2)
#define GSM_BYTES (2 * B_BYTES + 4 * A_BYTES)   // 208896

// ---------------- device scratch ----------------
__device__ float g_x[MROWS * IND];
__device__ float g_h[MROWS * HD];
__device__ float g_hout[MROWS * HD];
__device__ float g_el[MROWS * HH];
__device__ float g_er[MROWS * HH];
__device__ int   g_rowstart[NN + 1];
__device__ int   g_csr_src[EE];
__device__ float g_part[NPART * HD];
__device__ float g_partsq[NPART * HD];
__device__ float g_scale[HD];
__device__ float g_shift[HD];
__device__ __nv_bfloat16 g_wthi[3 * HD * HD];
__device__ __nv_bfloat16 g_wtlo[3 * HD * HD];

__device__ __forceinline__ uint32_t s2u(const void* p) {
    uint32_t a;
    asm("{ .reg .u64 t; cvta.to.shared.u64 t, %1; cvt.u32.u64 %0, t; }" : "=r"(a) : "l"(p));
    return a;
}
__device__ __forceinline__ void ldsm4(uint32_t* r, uint32_t a) {
    asm volatile("ldmatrix.sync.aligned.m8n8.x4.shared.b16 {%0,%1,%2,%3}, [%4];"
                 : "=r"(r[0]), "=r"(r[1]), "=r"(r[2]), "=r"(r[3]) : "r"(a));
}
__device__ __forceinline__ void mma16816(float* c, const uint32_t* a, const uint32_t* b) {
    asm volatile(
        "mma.sync.aligned.m16n8k16.row.col.f32.bf16.bf16.f32 "
        "{%0,%1,%2,%3}, {%4,%5,%6,%7}, {%8,%9}, {%0,%1,%2,%3};"
        : "+f"(c[0]), "+f"(c[1]), "+f"(c[2]), "+f"(c[3])
        : "r"(a[0]), "r"(a[1]), "r"(a[2]), "r"(a[3]), "r"(b[0]), "r"(b[1]));
}
__device__ __forceinline__ float4 lrelu4(float4 a, float s) {
    a.x = a.x > 0.f ? a.x : s * a.x;
    a.y = a.y > 0.f ? a.y : s * a.y;
    a.z = a.z > 0.f ? a.z : s * a.z;
    a.w = a.w > 0.f ? a.w : s * a.w;
    return a;
}

// ---------------- CSR build (single block) ----------------
__global__ __launch_bounds__(1024) void k_csr(const int* __restrict__ src,
                                              const int* __restrict__ dst) {
    __shared__ int s_start[NN];
    __shared__ int s_tmp[1024];
    const int t = threadIdx.x;

    for (int i = t; i < NN; i += 1024) s_start[i] = 0;
    __syncthreads();
    for (int e = t; e < EE; e += 1024) atomicAdd(&s_start[dst[e]], 1);
    __syncthreads();

    int carry = 0;
    for (int base = 0; base < NN; base += 1024) {
        int v = (base + t < NN) ? s_start[base + t] : 0;
        s_tmp[t] = v;
        __syncthreads();
        for (int off = 1; off < 1024; off <<= 1) {
            int x = (t >= off) ? s_tmp[t - off] : 0;
            __syncthreads();
            s_tmp[t] += x;
            __syncthreads();
        }
        int incl = s_tmp[t];
        int tot = s_tmp[1023];
        __syncthreads();
        if (base + t < NN) {
            int ex = carry + incl - v;
            s_start[base + t] = ex;
            g_rowstart[base + t] = ex;
        }
        carry += tot;
    }
    if (t == 0) g_rowstart[NN] = carry;
    __syncthreads();

    for (int e = t; e < EE; e += 1024) {
        int v = dst[e];
        int p = atomicAdd(&s_start[v], 1);
        g_csr_src[p] = src[e];
    }
}

__global__ void k_copyx(const float* __restrict__ xx) {
    int i = blockIdx.x * blockDim.x + threadIdx.x;
    if (i < MROWS * IND) g_x[i] = xx[i];
}

// ---------------- W transpose + bf16 split ----------------
__global__ void k_wprep(const float* __restrict__ W1, const float* __restrict__ W2,
                        const float* __restrict__ W3) {
    int k = blockIdx.x;
    int l = blockIdx.y;
    int n = threadIdx.x;
    const float* W = (l == 0) ? W1 : (l == 1) ? W2 : W3;
    float v = W[k * HD + n];
    __nv_bfloat16 h = __float2bfloat16(v);
    float lo = v - __bfloat162float(h);
    int o = l * HD * HD + n * HD + k;
    g_wthi[o] = h;
    g_wtlo[o] = __float2bfloat16(lo);
}

// ---------------- layer-0 FC (32 rows/block) ----------------
__global__ __launch_bounds__(256) void k_fc0(const float* __restrict__ W,
                                             const float* __restrict__ al,
                                             const float* __restrict__ ar) {
    __shared__ float sW[IND * HD];
    __shared__ float sx[FC_ROWS * IND];
    __shared__ float pel[FC_ROWS][8], per_[FC_ROWS][8];
    const int t = threadIdx.x;
    const int m0 = blockIdx.x * FC_ROWS;
    const int w = t >> 5, lane = t & 31;

    for (int i = t; i < IND * HD; i += 256) sW[i] = W[i];
    for (int i = t; i < FC_ROWS * IND; i += 256) sx[i] = g_x[m0 * IND + i];
    __syncthreads();

    const float alv = __ldg(&al[t]);
    const float arv = __ldg(&ar[t]);

#pragma unroll
    for (int r = 0; r < FC_ROWS; r++) {
        float acc = 0.f;
#pragma unroll
        for (int k = 0; k < IND; k++) acc = fmaf(sx[r * IND + k], sW[k * HD + t], acc);
        g_h[(size_t)(m0 + r) * HD + t] = acc;
        float ve = acc * alv, vr = acc * arv;
#pragma unroll
        for (int off = 16; off; off >>= 1) {
            ve += __shfl_xor_sync(0xffffffffu, ve, off);
            vr += __shfl_xor_sync(0xffffffffu, vr, off);
        }
        if (lane == 0) { pel[r][w] = ve; per_[r][w] = vr; }
    }
    __syncthreads();
    if (t < FC_ROWS * HH) {
        int r = t >> 2, h = t & 3;
        g_el[(m0 + r) * HH + h] = pel[r][2 * h] + pel[r][2 * h + 1];
        g_er[(m0 + r) * HH + h] = per_[r][2 * h] + per_[r][2 * h + 1];
    }
}

// ---------------- HMMA GEMM (R10 exact): 512 threads, warp 32x32 ----------------
__global__ __launch_bounds__(512) void k_gemm(int wsel, const float* __restrict__ al,
                                              const float* __restrict__ ar) {
    extern __shared__ char sm[];
    __shared__ float s_sc[HD], s_sh[HD];
    __shared__ float sh_e[2][128][2][2];
    __nv_bfloat16* Bhi = (__nv_bfloat16*)sm;
    __nv_bfloat16* Blo = Bhi + 128 * BSTR;
    __nv_bfloat16* Abase = Blo + 128 * BSTR;
    const uint32_t uBhi = s2u(Bhi), uBlo = s2u(Blo);
    const uint32_t uA = s2u(Abase);

    const int t = threadIdx.x;
    const int lane = t & 31, warp = t >> 5;
    const int bx = blockIdx.x, by = blockIdx.y;
    const int row0 = by * TM, col0 = bx * TN;
    const int warp_m = (warp >> 2) * 32;
    const int warp_n = (warp & 3) * 32;
    const int head2 = (warp & 3) >> 1;
    const int halfid = warp & 1;
    const int head = bx * 2 + head2;

    if (t < HD) { s_sc[t] = g_scale[t]; s_sh[t] = g_shift[t]; }
    __syncthreads();

    const __nv_bfloat16* wh = g_wthi + wsel * HD * HD;
    const __nv_bfloat16* wl = g_wtlo + wsel * HD * HD;

    {
        int n = t >> 2, kq = (t & 3) * 64;
        int gn = col0 + n;
        const uint4* ph = (const uint4*)&wh[gn * HD + kq];
        const uint4* pl = (const uint4*)&wl[gn * HD + kq];
#pragma unroll
        for (int q = 0; q < 8; q++) {
            *(uint4*)&Bhi[n * BSTR + kq + 8 * q] = __ldg(&ph[q]);
            *(uint4*)&Blo[n * BSTR + kq + 8 * q] = __ldg(&pl[q]);
        }
    }

    float c[2][4][4];
#pragma unroll
    for (int i = 0; i < 2; i++)
#pragma unroll
        for (int j = 0; j < 4; j++)
#pragma unroll
            for (int q = 0; q < 4; q++) c[i][j][q] = 0.f;

    const int a_row = ((lane >> 3) & 1) * 8 + (lane & 7);
    const int a_kof = (lane >> 4) * 8;
    const int b_nsel = (lane >> 4) & 1;
    const int b_ksel = (lane >> 3) & 1;
    const int b_row = (lane & 7);

    auto convA = [&](int ch, int bf) {
        __nv_bfloat16* Ahi = Abase + bf * 2 * 128 * ASTR;
        __nv_bfloat16* Alo = Ahi + 128 * ASTR;
        const int k0 = ch * KC;
        int r = t >> 2, c0i = (t & 3) * 16;
        int grow = row0 + r;
        float x[16];
        if (grow < MROWS) {
            const float4* p = (const float4*)&g_hout[(size_t)grow * HD + k0 + c0i];
#pragma unroll
            for (int q = 0; q < 4; q++) {
                float4 v = p[q];
                x[4 * q + 0] = v.x; x[4 * q + 1] = v.y; x[4 * q + 2] = v.z; x[4 * q + 3] = v.w;
            }
        } else {
#pragma unroll
            for (int j = 0; j < 16; j++) x[j] = 0.f;
        }
#pragma unroll
        for (int j = 0; j < 16; j++) {
            float v = fmaf(x[j], s_sc[k0 + c0i + j], s_sh[k0 + c0i + j]);
            x[j] = v > 0.f ? v : 0.01f * v;
        }
#pragma unroll
        for (int q = 0; q < 2; q++) {
            union { __nv_bfloat16 b[8]; uint4 u; } uh, ul;
#pragma unroll
            for (int j = 0; j < 8; j++) {
                float xv = x[8 * q + j];
                __nv_bfloat16 h = __float2bfloat16(xv);
                uh.b[j] = h;
                ul.b[j] = __float2bfloat16(xv - __bfloat162float(h));
            }
            *(uint4*)&Ahi[r * ASTR + c0i + 8 * q] = uh.u;
            *(uint4*)&Alo[r * ASTR + c0i + 8 * q] = ul.u;
        }
    };

    convA(0, 0);
    __syncthreads();

    for (int ch = 0; ch < 4; ch++) {
        const int bf = ch & 1;
        const uint32_t uAhi = uA + (uint32_t)(bf * 2 * 128 * ASTR * 2);
        const uint32_t uAlo = uAhi + 128 * ASTR * 2;
#pragma unroll
        for (int ks = 0; ks < 4; ks++) {
            const int kg = ch * 4 + ks;
            uint32_t afh[2][4], afl[2][4];
            uint32_t bfh[4][2], bfl[4][2];
#pragma unroll
            for (int mt = 0; mt < 2; mt++) {
                uint32_t off = (uint32_t)(((warp_m + mt * 16 + a_row) * ASTR + 16 * ks + a_kof) * 2);
                ldsm4(afh[mt], uAhi + off);
                ldsm4(afl[mt], uAlo + off);
            }
#pragma unroll
            for (int p = 0; p < 2; p++) {
                uint32_t off = (uint32_t)(((warp_n + (2 * p + b_nsel) * 8 + b_row) * BSTR + 16 * kg + 8 * b_ksel) * 2);
                uint32_t r4[4];
                ldsm4(r4, uBhi + off);
                bfh[2 * p][0] = r4[0]; bfh[2 * p][1] = r4[1];
                bfh[2 * p + 1][0] = r4[2]; bfh[2 * p + 1][1] = r4[3];
                ldsm4(r4, uBlo + off);
                bfl[2 * p][0] = r4[0]; bfl[2 * p][1] = r4[1];
                bfl[2 * p + 1][0] = r4[2]; bfl[2 * p + 1][1] = r4[3];
            }
#pragma unroll
            for (int mt = 0; mt < 2; mt++)
#pragma unroll
                for (int nt = 0; nt < 4; nt++) {
                    mma16816(c[mt][nt], afh[mt], bfh[nt]);
                    mma16816(c[mt][nt], afh[mt], bfl[nt]);
                    mma16816(c[mt][nt], afl[mt], bfh[nt]);
                }
        }
        if (ch < 3) {
            convA(ch + 1, (ch + 1) & 1);
            __syncthreads();
        }
    }

    float elacc[2][2] = {{0.f, 0.f}, {0.f, 0.f}};
    float eracc[2][2] = {{0.f, 0.f}, {0.f, 0.f}};
    const int qn = 2 * (lane & 3);
    const int g = lane >> 2;
#pragma unroll
    for (int mt = 0; mt < 2; mt++) {
#pragma unroll
        for (int nt = 0; nt < 4; nt++) {
            float v0 = c[mt][nt][0], v1 = c[mt][nt][1];
            float v2 = c[mt][nt][2], v3 = c[mt][nt][3];
            int cih = nt * 8 + qn;
            int hcol = halfid * 32 + cih;
            float a0 = __ldg(&al[head * DD + hcol]), a1 = __ldg(&al[head * DD + hcol + 1]);
            float r0 = __ldg(&ar[head * DD + hcol]), r1 = __ldg(&ar[head * DD + hcol + 1]);
            elacc[mt][0] = fmaf(v0, a0, fmaf(v1, a1, elacc[mt][0]));
            elacc[mt][1] = fmaf(v2, a0, fmaf(v3, a1, elacc[mt][1]));
            eracc[mt][0] = fmaf(v0, r0, fmaf(v1, r1, eracc[mt][0]));
            eracc[mt][1] = fmaf(v2, r0, fmaf(v3, r1, eracc[mt][1]));
            int gcol = col0 + warp_n + cih;
            int grow0 = row0 + warp_m + mt * 16 + g;
            int grow1 = grow0 + 8;
            if (grow0 < MROWS) *(float2*)&g_h[(size_t)grow0 * HD + gcol] = make_float2(v0, v1);
            if (grow1 < MROWS) *(float2*)&g_h[(size_t)grow1 * HD + gcol] = make_float2(v2, v3);
        }
    }
#pragma unroll
    for (int mt = 0; mt < 2; mt++)
#pragma unroll
        for (int half = 0; half < 2; half++) {
            float e = elacc[mt][half], r = eracc[mt][half];
            e += __shfl_xor_sync(0xffffffffu, e, 1);
            e += __shfl_xor_sync(0xffffffffu, e, 2);
            r += __shfl_xor_sync(0xffffffffu, r, 1);
            r += __shfl_xor_sync(0xffffffffu, r, 2);
            if ((lane & 3) == 0) {
                int rr = warp_m + mt * 16 + half * 8 + g;
                sh_e[0][rr][head2][halfid] = e;
                sh_e[1][rr][head2][halfid] = r;
            }
        }
    __syncthreads();
    if (t < 256) {
        int rr = t & 127, h2 = t >> 7;
        int row = row0 + rr;
        if (row < MROWS) {
            g_el[row * HH + bx * 2 + h2] = sh_e[0][rr][h2][0] + sh_e[0][rr][h2][1];
            g_er[row * HH + bx * 2 + h2] = sh_e[1][rr][h2][0] + sh_e[1][rr][h2][1];
        }
    }
}

// ---------------- agg: warp/node, 8 nodes/CTA (R10 exact) ----------------
__global__ __launch_bounds__(256) void k_agg() {
    __shared__ float sh_a[8][32][4];
    __shared__ int   sh_src[8][32];
    __shared__ float sh_ws[8][HD];
    __shared__ float sh_wq[8][HD];

    const int t = threadIdx.x;
    const int w = t >> 5, lane = t & 31;
    const int bn = blockIdx.x * 8 + w;
    const int b = bn / NN, v = bn - b * NN;
    const int rowbase = b * NN;
    const int e0 = g_rowstart[v];
    const int deg = g_rowstart[v + 1] - e0;
    const int hc = lane >> 3;
    const int c0 = lane * 8;

    float4 accA = make_float4(0.f, 0.f, 0.f, 0.f);
    float4 accB = make_float4(0.f, 0.f, 0.f, 0.f);

    if (deg > 0) {
        const float4 erv = *(const float4*)&g_er[bn * HH];

        const bool has0 = lane < deg;
        int s0c = 0;
        float4 e0c = make_float4(-INFINITY, -INFINITY, -INFINITY, -INFINITY);
        if (has0) {
            s0c = g_csr_src[e0 + lane];
            float4 el = *(const float4*)&g_el[(rowbase + s0c) * HH];
            e0c = lrelu4(make_float4(el.x + erv.x, el.y + erv.y, el.z + erv.z, el.w + erv.w), 0.2f);
        }
        float4 m4 = e0c;
        for (int i = lane + 32; i < deg; i += 32) {
            int s = g_csr_src[e0 + i];
            float4 el = *(const float4*)&g_el[(rowbase + s) * HH];
            float4 e = lrelu4(make_float4(el.x + erv.x, el.y + erv.y, el.z + erv.z, el.w + erv.w), 0.2f);
            m4.x = fmaxf(m4.x, e.x); m4.y = fmaxf(m4.y, e.y);
            m4.z = fmaxf(m4.z, e.z); m4.w = fmaxf(m4.w, e.w);
        }
#pragma unroll
        for (int off = 16; off; off >>= 1) {
            m4.x = fmaxf(m4.x, __shfl_xor_sync(0xffffffffu, m4.x, off));
            m4.y = fmaxf(m4.y, __shfl_xor_sync(0xffffffffu, m4.y, off));
            m4.z = fmaxf(m4.z, __shfl_xor_sync(0xffffffffu, m4.z, off));
            m4.w = fmaxf(m4.w, __shfl_xor_sync(0xffffffffu, m4.w, off));
        }
        float4 s4 = make_float4(0.f, 0.f, 0.f, 0.f);
        if (has0) {
            float4 p = make_float4(__expf(e0c.x - m4.x), __expf(e0c.y - m4.y),
                                   __expf(e0c.z - m4.z), __expf(e0c.w - m4.w));
            s4 = p;
            sh_src[w][lane] = s0c;
            *(float4*)&sh_a[w][lane][0] = p;
        }
        for (int i = lane + 32; i < deg; i += 32) {
            int s = g_csr_src[e0 + i];
            float4 el = *(const float4*)&g_el[(rowbase + s) * HH];
            float4 e = lrelu4(make_float4(el.x + erv.x, el.y + erv.y, el.z + erv.z, el.w + erv.w), 0.2f);
            s4.x += __expf(e.x - m4.x); s4.y += __expf(e.y - m4.y);
            s4.z += __expf(e.z - m4.z); s4.w += __expf(e.w - m4.w);
        }
#pragma unroll
        for (int off = 16; off; off >>= 1) {
            s4.x += __shfl_xor_sync(0xffffffffu, s4.x, off);
            s4.y += __shfl_xor_sync(0xffffffffu, s4.y, off);
            s4.z += __shfl_xor_sync(0xffffffffu, s4.z, off);
            s4.w += __shfl_xor_sync(0xffffffffu, s4.w, off);
        }
        const float inv = 1.f / (hc == 0 ? s4.x : hc == 1 ? s4.y : hc == 2 ? s4.z : s4.w);
        const float mh  = (hc == 0 ? m4.x : hc == 1 ? m4.y : hc == 2 ? m4.z : m4.w);
        const float erh = (hc == 0 ? erv.x : hc == 1 ? erv.y : hc == 2 ? erv.z : erv.w);
        __syncwarp();

        const float* hb = g_h + (((size_t)rowbase) << 8) + c0;
        float4 acc2 = make_float4(0.f, 0.f, 0.f, 0.f);
        float4 acc3 = make_float4(0.f, 0.f, 0.f, 0.f);
        const int lim = min(deg, 32);
        int i = 0;
        for (; i + 4 <= lim; i += 4) {
            int sa = sh_src[w][i],     sb = sh_src[w][i + 1];
            int sc = sh_src[w][i + 2], sd = sh_src[w][i + 3];
            float wa = sh_a[w][i][hc] * inv,     wb = sh_a[w][i + 1][hc] * inv;
            float wc = sh_a[w][i + 2][hc] * inv, wd = sh_a[w][i + 3][hc] * inv;
            const float4* pa = (const float4*)(hb + ((size_t)sa << 8));
            const float4* pb = (const float4*)(hb + ((size_t)sb << 8));
            const float4* pc = (const float4*)(hb + ((size_t)sc << 8));
            const float4* pd = (const float4*)(hb + ((size_t)sd << 8));
            float4 a0 = pa[0], a1 = pa[1], b0 = pb[0], b1 = pb[1];
            float4 c0v = pc[0], c1 = pc[1], d0 = pd[0], d1 = pd[1];
            accA.x = fmaf(wa, a0.x, accA.x); accA.y = fmaf(wa, a0.y, accA.y);
            accA.z = fmaf(wa, a0.z, accA.z); accA.w = fmaf(wa, a0.w, accA.w);
            accB.x = fmaf(wa, a1.x, accB.x); accB.y = fmaf(wa, a1.y, accB.y);
            accB.z = fmaf(wa, a1.z, accB.z); accB.w = fmaf(wa, a1.w, accB.w);
            acc2.x = fmaf(wb, b0.x, acc2.x); acc2.y = fmaf(wb, b0.y, acc2.y);
            acc2.z = fmaf(wb, b0.z, acc2.z); acc2.w = fmaf(wb, b0.w, acc2.w);
            acc3.x = fmaf(wb, b1.x, acc3.x); acc3.y = fmaf(wb, b1.y, acc3.y);
            acc3.z = fmaf(wb, b1.z, acc3.z); acc3.w = fmaf(wb, b1.w, acc3.w);
            accA.x = fmaf(wc, c0v.x, accA.x); accA.y = fmaf(wc, c0v.y, accA.y);
            accA.z = fmaf(wc, c0v.z, accA.z); accA.w = fmaf(wc, c0v.w, accA.w);
            accB.x = fmaf(wc, c1.x, accB.x); accB.y = fmaf(wc, c1.y, accB.y);
            accB.z = fmaf(wc, c1.z, accB.z); accB.w = fmaf(wc, c1.w, accB.w);
            acc2.x = fmaf(wd, d0.x, acc2.x); acc2.y = fmaf(wd, d0.y, acc2.y);
            acc2.z = fmaf(wd, d0.z, acc2.z); acc2.w = fmaf(wd, d0.w, acc2.w);
            acc3.x = fmaf(wd, d1.x, acc3.x); acc3.y = fmaf(wd, d1.y, acc3.y);
            acc3.z = fmaf(wd, d1.z, acc3.z); acc3.w = fmaf(wd, d1.w, acc3.w);
        }
        for (; i < lim; i++) {
            int s = sh_src[w][i];
            float wv = sh_a[w][i][hc] * inv;
            const float4* p = (const float4*)(hb + ((size_t)s << 8));
            float4 h0 = p[0], h1 = p[1];
            accA.x = fmaf(wv, h0.x, accA.x); accA.y = fmaf(wv, h0.y, accA.y);
            accA.z = fmaf(wv, h0.z, accA.z); accA.w = fmaf(wv, h0.w, accA.w);
            accB.x = fmaf(wv, h1.x, accB.x); accB.y = fmaf(wv, h1.y, accB.y);
            accB.z = fmaf(wv, h1.z, accB.z); accB.w = fmaf(wv, h1.w, accB.w);
        }
        for (i = 32; i < deg; i++) {
            int s = g_csr_src[e0 + i];
            float4 el = *(const float4*)&g_el[(rowbase + s) * HH];
            float e = (hc == 0 ? el.x : hc == 1 ? el.y : hc == 2 ? el.z : el.w) + erh;
            e = e > 0.f ? e : 0.2f * e;
            float wv = __expf(e - mh) * inv;
            const float4* p = (const float4*)(hb + ((size_t)s << 8));
            float4 h0 = p[0], h1 = p[1];
            accA.x = fmaf(wv, h0.x, accA.x); accA.y = fmaf(wv, h0.y, accA.y);
            accA.z = fmaf(wv, h0.z, accA.z); accA.w = fmaf(wv, h0.w, accA.w);
            accB.x = fmaf(wv, h1.x, accB.x); accB.y = fmaf(wv, h1.y, accB.y);
            accB.z = fmaf(wv, h1.z, accB.z); accB.w = fmaf(wv, h1.w, accB.w);
        }
        accA.x += acc2.x; accA.y += acc2.y; accA.z += acc2.z; accA.w += acc2.w;
        accB.x += acc3.x; accB.y += acc3.y; accB.z += acc3.z; accB.w += acc3.w;
    }

    float* outp = g_hout + (size_t)bn * HD + c0;
    *(float4*)outp = accA;
    *(float4*)(outp + 4) = accB;

    *(float4*)&sh_ws[w][c0]     = accA;
    *(float4*)&sh_ws[w][c0 + 4] = accB;
    *(float4*)&sh_wq[w][c0]     = make_float4(accA.x * accA.x, accA.y * accA.y,
                                              accA.z * accA.z, accA.w * accA.w);
    *(float4*)&sh_wq[w][c0 + 4] = make_float4(accB.x * accB.x, accB.y * accB.y,
                                              accB.z * accB.z, accB.w * accB.w);
    __syncthreads();
    if (t < HD) {
        float s = 0.f, sq = 0.f;
#pragma unroll
        for (int wi = 0; wi < 8; wi++) { s += sh_ws[wi][t]; sq += sh_wq[wi][t]; }
        int slot = (blockIdx.x & (NPART - 1)) * HD + t;
        atomicAdd(&g_part[slot], s);
        atomicAdd(&g_partsq[slot], sq);
    }
}

// ---------------- BatchNorm finalize ----------------
__global__ void k_bnfin(const float* __restrict__ gamma, const float* __restrict__ beta) {
    int c = threadIdx.x;
    float s = 0.f, sq = 0.f;
#pragma unroll
    for (int i = 0; i < NPART; i++) {
        s  += g_part[i * HD + c];
        sq += g_partsq[i * HD + c];
        g_part[i * HD + c] = 0.f;
        g_partsq[i * HD + c] = 0.f;
    }
    float inv = 1.f / (float)MROWS;
    float mu = s * inv;
    float var = sq * inv - mu * mu;
    float sc = gamma[c] * rsqrtf(var + EPSBN);
    g_scale[c] = sc;
    g_shift[c] = beta[c] - mu * sc;
}

// ---------------- output projection: warp per node, 8 nodes/CTA ----------------
__global__ __launch_bounds__(256) void k_proj(const float* __restrict__ Wo,
                                              const float* __restrict__ bo,
                                              float* __restrict__ out, int step) {
    __shared__ float sWo[HD * OUTD];
    const int t = threadIdx.x;
    const int lane = t & 31;
    const int bn = blockIdx.x * 8 + (t >> 5);

    for (int i = t; i < HD * OUTD; i += 256) sWo[i] = Wo[i];
    __syncthreads();

    const float* hp = g_hout + (size_t)bn * HD;
    float s0 = 0.f, s1 = 0.f, s2 = 0.f;
#pragma unroll
    for (int q = 0; q < 8; q++) {
        int k = lane * 8 + q;
        float xv = fmaf(hp[k], g_scale[k], g_shift[k]);
        xv = xv > 0.f ? xv : 0.01f * xv;
        s0 = fmaf(xv, sWo[k * OUTD + 0], s0);
        s1 = fmaf(xv, sWo[k * OUTD + 1], s1);
        s2 = fmaf(xv, sWo[k * OUTD + 2], s2);
    }
#pragma unroll
    for (int off = 16; off; off >>= 1) {
        s0 += __shfl_xor_sync(0xffffffffu, s0, off);
        s1 += __shfl_xor_sync(0xffffffffu, s1, off);
        s2 += __shfl_xor_sync(0xffffffffu, s2, off);
    }
    s0 += __ldg(&bo[0]); s1 += __ldg(&bo[1]); s2 += __ldg(&bo[2]);

    float keep = 0.f;
    if (lane < IND - OUTD) keep = g_x[bn * IND + lane + OUTD];
    __syncwarp();
    if (lane < IND - OUTD) g_x[bn * IND + lane] = keep;
    else if (lane < IND) g_x[bn * IND + lane] = (lane == 27 ? s0 : lane == 28 ? s1 : s2);
    if (lane < OUTD) out[(bn * TSTEPS + step) * OUTD + lane] = (lane == 0 ? s0 : lane == 1 ? s1 : s2);
}

// ---------------- launcher ----------------
extern "C" void kernel_launch(void* const* d_in, const int* in_sizes, int n_in,
                              void* d_out, int out_size) {
    const float* xx  = (const float*)d_in[0];
    const int*   src = (const int*)d_in[1];
    const int*   dst = (const int*)d_in[2];
    const float *W[4], *al[4], *ar[4], *gamma[4], *beta[4];
    for (int l = 0; l < 4; l++) {
        W[l]     = (const float*)d_in[3 + 5 * l];
        al[l]    = (const float*)d_in[4 + 5 * l];
        ar[l]    = (const float*)d_in[5 + 5 * l];
        gamma[l] = (const float*)d_in[6 + 5 * l];
        beta[l]  = (const float*)d_in[7 + 5 * l];
    }
    const float* W_out = (const float*)d_in[23];
    const float* b_out = (const float*)d_in[24];
    float* out = (float*)d_out;

    cudaFuncSetAttribute(k_gemm, cudaFuncAttributeMaxDynamicSharedMemorySize, GSM_BYTES);

    dim3 ggrid(HD / TN, (MROWS + TM - 1) / TM);   // (2, 313)

    k_csr<<<1, 1024>>>(src, dst);                                // 1
    k_copyx<<<(MROWS * IND + 255) / 256, 256>>>(xx);             // 2
    k_fc0<<<MROWS / FC_ROWS, 256>>>(W[0], al[0], ar[0]);         // 3
    k_agg<<<MROWS / 8, 256>>>();                                 // 4  <-- profiled
    k_wprep<<<dim3(HD, 3), HD>>>(W[1], W[2], W[3]);              // 5
    k_bnfin<<<1, HD>>>(gamma[0], beta[0]);                       // 6
    for (int l = 1; l < 4; l++) {
        k_gemm<<<ggrid, 512, GSM_BYTES>>>(l - 1, al[l], ar[l]);
        k_agg<<<MROWS / 8, 256>>>();
        k_bnfin<<<1, HD>>>(gamma[l], beta[l]);
    }
    k_proj<<<MROWS / 8, 256>>>(W_out, b_out, out, 0);

    for (int step = 1; step < TSTEPS; step++) {
        for (int l = 0; l < 4; l++) {
            if (l == 0)
                k_fc0<<<MROWS / FC_ROWS, 256>>>(W[0], al[0], ar[0]);
            else
                k_gemm<<<ggrid, 512, GSM_BYTES>>>(l - 1, al[l], ar[l]);
            k_agg<<<MROWS / 8, 256>>>();
            k_bnfin<<<1, HD>>>(gamma[l], beta[l]);
        }
        k_proj<<<MROWS / 8, 256>>>(W_out, b_out, out, step);
    }
}